// round 2
// baseline (speedup 1.0000x reference)
#include <cuda_runtime.h>

// SSIM loss, fused single-pass implementation.
// Inputs (metadata order): d_in[0] = sr_image (16,3,512,512) f32,
//                          d_in[1] = hr_image (16,3,512,512) f32.
// Only channel 0 of each is used. Output: 1 float (mean SSIM over 16x502x502).

#define IMG        512
#define OUT_DIM    502
#define TILE       32
#define IN_TILE    42          // TILE + 10 halo
#define KSIZE      11
#define NIMG       16

// 1D Gaussian, sigma=1.5, size=11, normalized (outer product == 2D fspecial_gauss).
__constant__ float c_w[KSIZE] = {
    0.001028380f, 0.007598758f, 0.036000773f, 0.109360702f, 0.213005529f,
    0.266011716f,
    0.213005529f, 0.109360702f, 0.036000773f, 0.007598758f, 0.001028380f
};

__device__ double g_acc;

__global__ void zero_kernel() { g_acc = 0.0; }

__global__ void final_kernel(float* out) {
    out[0] = (float)(g_acc / (double)(NIMG * OUT_DIM * OUT_DIM));
}

__global__ __launch_bounds__(256, 1)
void ssim_kernel(const float* __restrict__ sr, const float* __restrict__ hr)
{
    // hr is image1, sr is image2 (formula is symmetric anyway).
    __shared__ float s_a[IN_TILE * IN_TILE];   // hr tile
    __shared__ float s_b[IN_TILE * IN_TILE];   // sr tile
    __shared__ float s_t[5][IN_TILE * TILE];   // horizontally-convolved: m1,m2,x2,y2,xy
    __shared__ float s_red[8];

    const int n   = blockIdx.z;
    const int oy0 = blockIdx.y * TILE;
    const int ox0 = blockIdx.x * TILE;
    const size_t img_base = (size_t)n * 3 * IMG * IMG;  // channel 0 of image n
    const float* A = hr + img_base;
    const float* B = sr + img_base;

    const int tid = threadIdx.x + threadIdx.y * 32;

    // ---- Phase 1: load 42x42 input tiles (zero-pad out of range; those pixels
    //               only feed invalid outputs which are masked later) ----
    for (int idx = tid; idx < IN_TILE * IN_TILE; idx += 256) {
        int r = idx / IN_TILE, c = idx % IN_TILE;
        int gy = oy0 + r, gx = ox0 + c;
        float a = 0.f, b = 0.f;
        if (gy < IMG && gx < IMG) {
            a = A[gy * IMG + gx];
            b = B[gy * IMG + gx];
        }
        s_a[idx] = a;
        s_b[idx] = b;
    }
    __syncthreads();

    // ---- Phase 2: horizontal Gaussian pass on 5 quantities (42 rows x 32 cols) ----
    for (int idx = tid; idx < IN_TILE * TILE; idx += 256) {
        int r = idx / TILE, c = idx % TILE;
        const float* pa = s_a + r * IN_TILE + c;
        const float* pb = s_b + r * IN_TILE + c;
        float m1 = 0.f, m2 = 0.f, x2 = 0.f, y2 = 0.f, xy = 0.f;
        #pragma unroll
        for (int k = 0; k < KSIZE; k++) {
            float w = c_w[k];
            float a = pa[k];
            float b = pb[k];
            float wa = w * a;
            float wb = w * b;
            m1 += wa;
            m2 += wb;
            x2 = fmaf(wa, a, x2);
            y2 = fmaf(wb, b, y2);
            xy = fmaf(wa, b, xy);
        }
        s_t[0][idx] = m1;
        s_t[1][idx] = m2;
        s_t[2][idx] = x2;
        s_t[3][idx] = y2;
        s_t[4][idx] = xy;
    }
    __syncthreads();

    // ---- Phase 3: vertical pass, 4 output rows per thread (rows ty*4 .. ty*4+3,
    //               column tx). Reads 14 intermediate rows once each. ----
    const int tx  = threadIdx.x;
    const int ry0 = threadIdx.y * 4;

    float sum[4][5];
    #pragma unroll
    for (int j = 0; j < 4; j++)
        #pragma unroll
        for (int q = 0; q < 5; q++)
            sum[j][q] = 0.f;

    #pragma unroll
    for (int rr = 0; rr < 14; rr++) {
        int row = ry0 + rr;
        float v0 = s_t[0][row * TILE + tx];
        float v1 = s_t[1][row * TILE + tx];
        float v2 = s_t[2][row * TILE + tx];
        float v3 = s_t[3][row * TILE + tx];
        float v4 = s_t[4][row * TILE + tx];
        #pragma unroll
        for (int j = 0; j < 4; j++) {
            int k = rr - j;
            if (k >= 0 && k < KSIZE) {      // compile-time resolved
                float w = c_w[k];
                sum[j][0] = fmaf(w, v0, sum[j][0]);
                sum[j][1] = fmaf(w, v1, sum[j][1]);
                sum[j][2] = fmaf(w, v2, sum[j][2]);
                sum[j][3] = fmaf(w, v3, sum[j][3]);
                sum[j][4] = fmaf(w, v4, sum[j][4]);
            }
        }
    }

    // ---- SSIM per pixel + accumulate ----
    const float C1 = 1e-4f;   // (0.01*1)^2
    const float C2 = 9e-4f;   // (0.03*1)^2
    float local = 0.f;
    #pragma unroll
    for (int j = 0; j < 4; j++) {
        int gy = oy0 + ry0 + j;
        int gx = ox0 + tx;
        if (gy < OUT_DIM && gx < OUT_DIM) {
            float mu1  = sum[j][0];
            float mu2  = sum[j][1];
            float mu1s = mu1 * mu1;
            float mu2s = mu2 * mu2;
            float mu12 = mu1 * mu2;
            float s1   = sum[j][2] - mu1s;
            float s2   = sum[j][3] - mu2s;
            float s12  = sum[j][4] - mu12;
            float num  = (2.f * mu12 + C1) * (2.f * s12 + C2);
            float den  = (mu1s + mu2s + C1) * (s1 + s2 + C2);
            local += num / den;
        }
    }

    // ---- Block reduction -> global double accumulator ----
    #pragma unroll
    for (int off = 16; off > 0; off >>= 1)
        local += __shfl_down_sync(0xffffffffu, local, off);
    if (threadIdx.x == 0)
        s_red[threadIdx.y] = local;
    __syncthreads();
    if (tid == 0) {
        float t = 0.f;
        #pragma unroll
        for (int i = 0; i < 8; i++) t += s_red[i];
        atomicAdd(&g_acc, (double)t);
    }
}

extern "C" void kernel_launch(void* const* d_in, const int* in_sizes, int n_in,
                              void* d_out, int out_size)
{
    const float* sr = (const float*)d_in[0];
    const float* hr = (const float*)d_in[1];

    zero_kernel<<<1, 1>>>();
    dim3 grid(16, 16, NIMG);
    dim3 block(32, 8);
    ssim_kernel<<<grid, block>>>(sr, hr);
    final_kernel<<<1, 1>>>((float*)d_out);
}

// round 3
// speedup vs baseline: 1.6461x; 1.6461x over previous
#include <cuda_runtime.h>

// SSIM loss — single fused kernel.
// d_in[0] = sr_image (16,3,512,512) f32, d_in[1] = hr_image (16,3,512,512) f32.
// Only channel 0 used. Output: 1 float = mean SSIM over (16,1,502,502).

#define IMG     512
#define OUT_DIM 502
#define TX      32
#define TY      32
#define INX     42          // TX + 10
#define INY     42          // TY + 10
#define ST_AB   43          // float2 row stride for input tile (odd -> conflict-free)
#define ST_T    33          // row stride for intermediates (odd)
#define NBX     16
#define NBY     16
#define NIMG    16
#define NBLK    (NBX * NBY * NIMG)

__device__ float        g_part[NBLK];
__device__ unsigned int g_count = 0;

// ---- packed f32x2 helpers (Blackwell fma.rn.f32x2 path) ----
typedef unsigned long long ull;

static __device__ __forceinline__ ull pk2(float x, float y) {
    ull r; asm("mov.b64 %0, {%1, %2};" : "=l"(r) : "f"(x), "f"(y)); return r;
}
static __device__ __forceinline__ void upk2(ull v, float& x, float& y) {
    asm("mov.b64 {%0, %1}, %2;" : "=f"(x), "=f"(y) : "l"(v));
}
static __device__ __forceinline__ ull fma2(ull a, ull b, ull c) {
    ull d; asm("fma.rn.f32x2 %0, %1, %2, %3;" : "=l"(d) : "l"(a), "l"(b), "l"(c)); return d;
}
static __device__ __forceinline__ ull mul2(ull a, ull b) {
    ull d; asm("mul.rn.f32x2 %0, %1, %2;" : "=l"(d) : "l"(a), "l"(b)); return d;
}

__global__ __launch_bounds__(256, 4)
void ssim_kernel(const float* __restrict__ sr, const float* __restrict__ hr,
                 float* __restrict__ out)
{
    // 1D Gaussian (sigma=1.5, size=11), normalized; outer product == fspecial_gauss.
    // constexpr so weights become immediates, not LDC.
    constexpr float W[11] = {
        0.001028380f, 0.007598758f, 0.036000773f, 0.109360702f, 0.213005529f,
        0.266011716f,
        0.213005529f, 0.109360702f, 0.036000773f, 0.007598758f, 0.001028380f
    };

    __shared__ float2 s_ab[INY * ST_AB];   // (hr, sr) interleaved          14448 B
    __shared__ float2 s_mm[INY * ST_T];    // horiz (mu1, mu2)              11088 B
    __shared__ float2 s_ss[INY * ST_T];    // horiz (E[x^2], E[y^2])        11088 B
    __shared__ float  s_xy[INY * ST_T];    // horiz E[xy]                    5544 B
    __shared__ float  s_wsum[8];
    __shared__ double s_dred[8];
    __shared__ int    s_last;

    const int tid = threadIdx.x;
    const int bx  = blockIdx.x, by = blockIdx.y, bz = blockIdx.z;
    const int oy0 = by * TY;
    const int ox0 = bx * TX;
    const size_t img_base = (size_t)bz * 3 * IMG * IMG;   // channel 0
    const float* __restrict__ A = hr + img_base;
    const float* __restrict__ B = sr + img_base;

    // ---------------- Phase 1: stage 42x42 (a,b) tile as interleaved float2 ----
    for (int idx = tid; idx < INY * INX; idx += 256) {
        int r = idx / INX;
        int c = idx - r * INX;
        int gy = oy0 + r, gx = ox0 + c;
        float a = 0.f, b = 0.f;
        if (gy < IMG && gx < IMG) {
            int g = gy * IMG + gx;
            a = A[g];
            b = B[g];
        }
        s_ab[r * ST_AB + c] = make_float2(a, b);
    }
    __syncthreads();

    // ---------------- Phase 2: horizontal pass, sliding window, 4 outputs/item -
    // item idx = seg*42 + row : consecutive threads -> consecutive rows
    for (int idx = tid; idx < 8 * INY; idx += 256) {
        int seg = idx / INY;           // 0..7
        int row = idx - seg * INY;     // 0..41
        int c0  = seg * 4;
        const float2* p = &s_ab[row * ST_AB + c0];

        ull   mm[4] = {0, 0, 0, 0};
        ull   ss[4] = {0, 0, 0, 0};
        float xy[4] = {0.f, 0.f, 0.f, 0.f};

        #pragma unroll
        for (int e = 0; e < 14; e++) {
            float2 v  = p[e];
            ull    pv = pk2(v.x, v.y);
            ull    sq = mul2(pv, pv);
            float  ab = v.x * v.y;
            #pragma unroll
            for (int j = 0; j < 4; j++) {
                int k = e - j;                      // compile-time resolved
                if (k >= 0 && k < 11) {
                    ull ww = pk2(W[k], W[k]);
                    mm[j] = fma2(ww, pv, mm[j]);
                    ss[j] = fma2(ww, sq, ss[j]);
                    xy[j] = fmaf(W[k], ab, xy[j]);
                }
            }
        }
        #pragma unroll
        for (int j = 0; j < 4; j++) {
            int o = row * ST_T + c0 + j;
            float x, y;
            upk2(mm[j], x, y);  s_mm[o] = make_float2(x, y);
            upk2(ss[j], x, y);  s_ss[o] = make_float2(x, y);
            s_xy[o] = xy[j];
        }
    }
    __syncthreads();

    // ---------------- Phase 3: vertical pass, 4 output rows per thread ---------
    const int c  = tid & 31;           // column (consecutive threads -> cf banks)
    const int r0 = (tid >> 5) * 4;     // first output row of this thread

    ull   vm[4] = {0, 0, 0, 0};
    ull   vs[4] = {0, 0, 0, 0};
    float vx[4] = {0.f, 0.f, 0.f, 0.f};

    #pragma unroll
    for (int e = 0; e < 14; e++) {
        int o = (r0 + e) * ST_T + c;
        float2 m = s_mm[o];
        float2 s = s_ss[o];
        float  x = s_xy[o];
        ull pm = pk2(m.x, m.y);
        ull ps = pk2(s.x, s.y);
        #pragma unroll
        for (int j = 0; j < 4; j++) {
            int k = e - j;
            if (k >= 0 && k < 11) {
                ull ww = pk2(W[k], W[k]);
                vm[j] = fma2(ww, pm, vm[j]);
                vs[j] = fma2(ww, ps, vs[j]);
                vx[j] = fmaf(W[k], x, vx[j]);
            }
        }
    }

    // ---------------- SSIM formula + accumulate --------------------------------
    const float C1 = 1e-4f;   // (0.01*1)^2
    const float C2 = 9e-4f;   // (0.03*1)^2
    float local = 0.f;
    #pragma unroll
    for (int j = 0; j < 4; j++) {
        int gy = oy0 + r0 + j;
        int gx = ox0 + c;
        if (gy < OUT_DIM && gx < OUT_DIM) {
            float mu1, mu2, ex2, ey2;
            upk2(vm[j], mu1, mu2);
            upk2(vs[j], ex2, ey2);
            float mu1s = mu1 * mu1;
            float mu2s = mu2 * mu2;
            float mu12 = mu1 * mu2;
            float sig1 = ex2 - mu1s;
            float sig2 = ey2 - mu2s;
            float s12  = vx[j] - mu12;
            float num  = (2.f * mu12 + C1) * (2.f * s12 + C2);
            float den  = (mu1s + mu2s + C1) * (sig1 + sig2 + C2);
            local += num / den;
        }
    }

    // block reduction
    #pragma unroll
    for (int off = 16; off > 0; off >>= 1)
        local += __shfl_down_sync(0xffffffffu, local, off);
    if ((tid & 31) == 0)
        s_wsum[tid >> 5] = local;
    __syncthreads();

    const int bid = bx + NBX * (by + NBY * bz);
    if (tid == 0) {
        float t = 0.f;
        #pragma unroll
        for (int i = 0; i < 8; i++) t += s_wsum[i];
        g_part[bid] = t;
        __threadfence();
        unsigned old = atomicInc(&g_count, NBLK - 1);   // wraps to 0 on last
        s_last = (old == NBLK - 1);
    }
    __syncthreads();

    // ---------------- Last block: deterministic final reduce -------------------
    if (s_last) {
        double d = 0.0;
        for (int i = tid; i < NBLK; i += 256)
            d += (double)__ldcg(&g_part[i]);
        #pragma unroll
        for (int off = 16; off > 0; off >>= 1)
            d += __shfl_down_sync(0xffffffffu, d, off);
        if ((tid & 31) == 0)
            s_dred[tid >> 5] = d;
        __syncthreads();
        if (tid == 0) {
            double s = 0.0;
            #pragma unroll
            for (int i = 0; i < 8; i++) s += s_dred[i];
            out[0] = (float)(s / ((double)NIMG * OUT_DIM * OUT_DIM));
        }
    }
}

extern "C" void kernel_launch(void* const* d_in, const int* in_sizes, int n_in,
                              void* d_out, int out_size)
{
    const float* sr = (const float*)d_in[0];
    const float* hr = (const float*)d_in[1];
    dim3 grid(NBX, NBY, NIMG);
    ssim_kernel<<<grid, 256>>>(sr, hr, (float*)d_out);
}

// round 4
// speedup vs baseline: 1.7779x; 1.0801x over previous
#include <cuda_runtime.h>

// SSIM loss — single fused kernel.
// d_in[0] = sr_image (16,3,512,512) f32, d_in[1] = hr_image (16,3,512,512) f32.
// Only channel 0 used. Output: 1 float = mean SSIM over (16,1,502,502).

#define IMG     512
#define OUT_DIM 502
#define TX      32
#define TY      32
#define INX     42          // TX + 10
#define INY     42          // TY + 10
#define ST_AB   43          // float2 row stride for input tile (odd -> conflict-free)
#define ST_T    33          // row stride for intermediates (odd)
#define NBX     16
#define NBY     16
#define NIMG    16
#define NBLK    (NBX * NBY * NIMG)

__device__ float        g_part[NBLK];
__device__ unsigned int g_count = 0;

// ---- packed f32x2 helpers (Blackwell fma.rn.f32x2 path) ----
typedef unsigned long long ull;

static __device__ __forceinline__ ull pk2(float x, float y) {
    ull r; asm("mov.b64 %0, {%1, %2};" : "=l"(r) : "f"(x), "f"(y)); return r;
}
static __device__ __forceinline__ void upk2(ull v, float& x, float& y) {
    asm("mov.b64 {%0, %1}, %2;" : "=f"(x), "=f"(y) : "l"(v));
}
static __device__ __forceinline__ ull fma2(ull a, ull b, ull c) {
    ull d; asm("fma.rn.f32x2 %0, %1, %2, %3;" : "=l"(d) : "l"(a), "l"(b), "l"(c)); return d;
}
static __device__ __forceinline__ ull mul2(ull a, ull b) {
    ull d; asm("mul.rn.f32x2 %0, %1, %2;" : "=l"(d) : "l"(a), "l"(b)); return d;
}

__global__ __launch_bounds__(256, 5)
void ssim_kernel(const float* __restrict__ sr, const float* __restrict__ hr,
                 float* __restrict__ out)
{
    // 1D Gaussian (sigma=1.5, size=11), normalized; outer product == fspecial_gauss.
    constexpr float W[11] = {
        0.001028380f, 0.007598758f, 0.036000773f, 0.109360702f, 0.213005529f,
        0.266011716f,
        0.213005529f, 0.109360702f, 0.036000773f, 0.007598758f, 0.001028380f
    };

    __shared__ float2 s_ab[INY * ST_AB + 8];  // (hr, sr) interleaved (+pad: last-seg window overrun)
    __shared__ float2 s_mm[INY * ST_T];       // horiz (mu1, mu2)
    __shared__ float2 s_ss[INY * ST_T];       // horiz (E[x^2], E[y^2])
    __shared__ float  s_xy[INY * ST_T];       // horiz E[xy]
    __shared__ float  s_wsum[8];
    __shared__ double s_dred[8];
    __shared__ int    s_last;

    const int tid = threadIdx.x;
    const int bx  = blockIdx.x, by = blockIdx.y, bz = blockIdx.z;
    const int oy0 = by * TY;
    const int ox0 = bx * TX;
    const size_t img_base = (size_t)bz * 3 * IMG * IMG;   // channel 0
    const float* __restrict__ A = hr + img_base;
    const float* __restrict__ B = sr + img_base;

    // ---------------- Phase 1: stage 42x42 (a,b) tile as interleaved float2 ----
    for (int idx = tid; idx < INY * INX; idx += 256) {
        int r = idx / INX;
        int c = idx - r * INX;
        int gy = oy0 + r, gx = ox0 + c;
        float a = 0.f, b = 0.f;
        if (gy < IMG && gx < IMG) {
            int g = gy * IMG + gx;
            a = A[g];
            b = B[g];
        }
        s_ab[r * ST_AB + c] = make_float2(a, b);
    }
    __syncthreads();

    // ---------------- Phase 2: horizontal pass, 6-wide sliding window ----------
    // 6 segments x 6 cols (cols 32..35 computed, discarded) x 42 rows = 252 items
    // -> single balanced wave over 256 threads.
    if (tid < 252) {
        int seg = tid / INY;           // 0..5
        int row = tid - seg * INY;     // 0..41
        int c0  = seg * 6;
        const float2* p = &s_ab[row * ST_AB + c0];

        ull   mm[6] = {0, 0, 0, 0, 0, 0};
        ull   ss[6] = {0, 0, 0, 0, 0, 0};
        float xy[6] = {0.f, 0.f, 0.f, 0.f, 0.f, 0.f};

        #pragma unroll
        for (int e = 0; e < 16; e++) {
            float2 v  = p[e];
            ull    pv = pk2(v.x, v.y);
            ull    sq = mul2(pv, pv);
            float  ab = v.x * v.y;
            #pragma unroll
            for (int j = 0; j < 6; j++) {
                int k = e - j;                      // compile-time resolved
                if (k >= 0 && k < 11) {
                    ull ww = pk2(W[k], W[k]);
                    mm[j] = fma2(ww, pv, mm[j]);
                    ss[j] = fma2(ww, sq, ss[j]);
                    xy[j] = fmaf(W[k], ab, xy[j]);
                }
            }
        }
        #pragma unroll
        for (int j = 0; j < 6; j++) {
            int col = c0 + j;
            if (col < TX) {
                int o = row * ST_T + col;
                float x, y;
                upk2(mm[j], x, y);  s_mm[o] = make_float2(x, y);
                upk2(ss[j], x, y);  s_ss[o] = make_float2(x, y);
                s_xy[o] = xy[j];
            }
        }
    }
    __syncthreads();

    // ---------------- Phase 3: vertical pass, 4 output rows per thread ---------
    const int c  = tid & 31;           // column
    const int r0 = (tid >> 5) * 4;     // first output row of this thread

    ull   vm[4] = {0, 0, 0, 0};
    ull   vs[4] = {0, 0, 0, 0};
    float vx[4] = {0.f, 0.f, 0.f, 0.f};

    #pragma unroll
    for (int e = 0; e < 14; e++) {
        int o = (r0 + e) * ST_T + c;
        float2 m = s_mm[o];
        float2 s = s_ss[o];
        float  x = s_xy[o];
        ull pm = pk2(m.x, m.y);
        ull ps = pk2(s.x, s.y);
        #pragma unroll
        for (int j = 0; j < 4; j++) {
            int k = e - j;
            if (k >= 0 && k < 11) {
                ull ww = pk2(W[k], W[k]);
                vm[j] = fma2(ww, pm, vm[j]);
                vs[j] = fma2(ww, ps, vs[j]);
                vx[j] = fmaf(W[k], x, vx[j]);
            }
        }
    }

    // ---------------- SSIM formula + accumulate --------------------------------
    const float C1 = 1e-4f;   // (0.01*1)^2
    const float C2 = 9e-4f;   // (0.03*1)^2
    float local = 0.f;
    #pragma unroll
    for (int j = 0; j < 4; j++) {
        int gy = oy0 + r0 + j;
        int gx = ox0 + c;
        if (gy < OUT_DIM && gx < OUT_DIM) {
            float mu1, mu2, ex2, ey2;
            upk2(vm[j], mu1, mu2);
            upk2(vs[j], ex2, ey2);
            float mu1s = mu1 * mu1;
            float mu2s = mu2 * mu2;
            float mu12 = mu1 * mu2;
            float sig1 = ex2 - mu1s;
            float sig2 = ey2 - mu2s;
            float s12  = vx[j] - mu12;
            float num  = (2.f * mu12 + C1) * (2.f * s12 + C2);
            float den  = (mu1s + mu2s + C1) * (sig1 + sig2 + C2);
            local += num / den;
        }
    }

    // block reduction
    #pragma unroll
    for (int off = 16; off > 0; off >>= 1)
        local += __shfl_down_sync(0xffffffffu, local, off);
    if ((tid & 31) == 0)
        s_wsum[tid >> 5] = local;
    __syncthreads();

    const int bid = bx + NBX * (by + NBY * bz);
    if (tid == 0) {
        float t = 0.f;
        #pragma unroll
        for (int i = 0; i < 8; i++) t += s_wsum[i];
        g_part[bid] = t;
        __threadfence();
        unsigned old = atomicInc(&g_count, NBLK - 1);   // wraps to 0 on last
        s_last = (old == NBLK - 1);
    }
    __syncthreads();

    // ---------------- Last block: deterministic final reduce -------------------
    if (s_last) {
        double d = 0.0;
        for (int i = tid; i < NBLK; i += 256)
            d += (double)__ldcg(&g_part[i]);
        #pragma unroll
        for (int off = 16; off > 0; off >>= 1)
            d += __shfl_down_sync(0xffffffffu, d, off);
        if ((tid & 31) == 0)
            s_dred[tid >> 5] = d;
        __syncthreads();
        if (tid == 0) {
            double s = 0.0;
            #pragma unroll
            for (int i = 0; i < 8; i++) s += s_dred[i];
            out[0] = (float)(s / ((double)NIMG * OUT_DIM * OUT_DIM));
        }
    }
}

extern "C" void kernel_launch(void* const* d_in, const int* in_sizes, int n_in,
                              void* d_out, int out_size)
{
    const float* sr = (const float*)d_in[0];
    const float* hr = (const float*)d_in[1];
    dim3 grid(NBX, NBY, NIMG);
    ssim_kernel<<<grid, 256>>>(sr, hr, (float*)d_out);
}

// round 6
// speedup vs baseline: 1.8603x; 1.0463x over previous
#include <cuda_runtime.h>

// SSIM loss — single fused kernel.
// d_in[0] = sr_image (16,3,512,512) f32, d_in[1] = hr_image (16,3,512,512) f32.
// Only channel 0 used. Output: 1 float = mean SSIM over (16,1,502,502).

#define IMG     512
#define OUT_DIM 502
#define TX      32
#define TY      32
#define INX     42          // TX + 10
#define INY     42          // TY + 10
#define ST_AB   43          // 64-bit-word row stride for input tile (odd -> conflict-free)
#define ST_T    33          // row stride for intermediates (odd)
#define NBX     16
#define NBY     16
#define NIMG    16
#define NBLK    (NBX * NBY * NIMG)

__device__ float        g_part[NBLK];
__device__ unsigned int g_count = 0;

// ---- packed f32x2 helpers (Blackwell fma.rn.f32x2 path) ----
typedef unsigned long long ull;

static __device__ __forceinline__ ull pk2(float x, float y) {
    ull r; asm("mov.b64 %0, {%1, %2};" : "=l"(r) : "f"(x), "f"(y)); return r;
}
static __device__ __forceinline__ void upk2(ull v, float& x, float& y) {
    asm("mov.b64 {%0, %1}, %2;" : "=f"(x), "=f"(y) : "l"(v));
}
static __device__ __forceinline__ ull fma2(ull a, ull b, ull c) {
    ull d; asm("fma.rn.f32x2 %0, %1, %2, %3;" : "=l"(d) : "l"(a), "l"(b), "l"(c)); return d;
}
static __device__ __forceinline__ ull mul2(ull a, ull b) {
    ull d; asm("mul.rn.f32x2 %0, %1, %2;" : "=l"(d) : "l"(a), "l"(b)); return d;
}

// 1D Gaussian (sigma=1.5, size=11), normalized; outer product == fspecial_gauss.
__device__ __forceinline__ constexpr float Wk(int k) {
    constexpr float W[11] = {
        0.001028380f, 0.007598758f, 0.036000773f, 0.109360702f, 0.213005529f,
        0.266011716f,
        0.213005529f, 0.109360702f, 0.036000773f, 0.007598758f, 0.001028380f
    };
    return (k >= 0 && k < 11) ? W[k] : 0.0f;
}

__global__ __launch_bounds__(256, 5)
void ssim_kernel(const float* __restrict__ sr, const float* __restrict__ hr,
                 float* __restrict__ out)
{
    __shared__ ull    s_ab[INY * ST_AB + 8];  // (hr, sr) packed (+pad: last-seg window overrun)
    __shared__ ull    s_mm[INY * ST_T];       // horiz (mu1, mu2) packed
    __shared__ ull    s_ss[INY * ST_T];       // horiz (E[x^2], E[y^2]) packed
    __shared__ float  s_xy[INY * ST_T];       // horiz E[xy]
    __shared__ float  s_wsum[8];
    __shared__ double s_dred[8];
    __shared__ int    s_last;

    const int tid = threadIdx.x;
    const int bx  = blockIdx.x, by = blockIdx.y, bz = blockIdx.z;
    const int oy0 = by * TY;
    const int ox0 = bx * TX;
    const size_t img_base = (size_t)bz * 3 * IMG * IMG;   // channel 0
    const float* __restrict__ A = hr + img_base;
    const float* __restrict__ B = sr + img_base;

    // ---------------- Phase 1: stage 42x42 (a,b) tile packed as 64-bit words ---
    #pragma unroll
    for (int it = 0; it < 7; it++) {
        int idx = tid + it * 256;
        if (idx < INY * INX) {
            int r = idx / INX;
            int c = idx - r * INX;
            int gy = oy0 + r, gx = ox0 + c;
            float a = 0.f, b = 0.f;
            if (gy < IMG && gx < IMG) {
                int g = gy * IMG + gx;
                a = A[g];
                b = B[g];
            }
            s_ab[r * ST_AB + c] = pk2(a, b);
        }
    }
    __syncthreads();

    // ---------------- Phase 2: horizontal pass, 6-wide sliding window ----------
    // 6 segments x 6 cols (cols 32..35 computed, discarded) x 42 rows = 252 items.
    if (tid < 252) {
        int seg = tid / INY;           // 0..5
        int row = tid - seg * INY;     // 0..41
        int c0  = seg * 6;
        const ull* p = &s_ab[row * ST_AB + c0];

        ull mm[6]  = {0, 0, 0, 0, 0, 0};
        ull ss[6]  = {0, 0, 0, 0, 0, 0};
        ull xyp[3] = {0, 0, 0};        // lanes: (xy0,xy1) (xy2,xy3) (xy4,xy5)

        #pragma unroll
        for (int e = 0; e < 16; e++) {
            ull pv = p[e];                       // LDS.64 -> aligned pair
            ull sq = mul2(pv, pv);
            float a, b; upk2(pv, a, b);
            ull abp = pk2(a * b, a * b);
            #pragma unroll
            for (int j = 0; j < 6; j++) {
                int k = e - j;                   // compile-time resolved
                if (k >= 0 && k < 11) {
                    ull ww = pk2(Wk(k), Wk(k));
                    mm[j] = fma2(ww, pv, mm[j]);
                    ss[j] = fma2(ww, sq, ss[j]);
                }
            }
            #pragma unroll
            for (int jp = 0; jp < 3; jp++) {
                int k0 = e - 2 * jp;             // weight for lane0 (col 2jp)
                if (k0 >= 0 && k0 < 12) {        // lane1 uses k0-1
                    ull wp = pk2(Wk(k0), Wk(k0 - 1));
                    xyp[jp] = fma2(wp, abp, xyp[jp]);
                }
            }
        }
        #pragma unroll
        for (int j = 0; j < 6; j++) {
            int col = c0 + j;
            if (col < TX) {
                int o = row * ST_T + col;
                s_mm[o] = mm[j];
                s_ss[o] = ss[j];
                float x0, x1; upk2(xyp[j >> 1], x0, x1);
                s_xy[o] = (j & 1) ? x1 : x0;
            }
        }
    }
    __syncthreads();

    // ---------------- Phase 3: vertical pass, 4 output rows per thread ---------
    const int c  = tid & 31;           // column
    const int r0 = (tid >> 5) * 4;     // first output row of this thread

    ull vm[4]  = {0, 0, 0, 0};
    ull vs[4]  = {0, 0, 0, 0};
    ull vxp[2] = {0, 0};               // lanes: (vx0,vx1) (vx2,vx3)

    #pragma unroll
    for (int e = 0; e < 14; e++) {
        int o = (r0 + e) * ST_T + c;
        ull pm = s_mm[o];
        ull ps = s_ss[o];
        float x = s_xy[o];
        ull xp = pk2(x, x);
        #pragma unroll
        for (int j = 0; j < 4; j++) {
            int k = e - j;
            if (k >= 0 && k < 11) {
                ull ww = pk2(Wk(k), Wk(k));
                vm[j] = fma2(ww, pm, vm[j]);
                vs[j] = fma2(ww, ps, vs[j]);
            }
        }
        #pragma unroll
        for (int jp = 0; jp < 2; jp++) {
            int k0 = e - 2 * jp;
            if (k0 >= 0 && k0 < 12) {
                ull wp = pk2(Wk(k0), Wk(k0 - 1));
                vxp[jp] = fma2(wp, xp, vxp[jp]);
            }
        }
    }

    // ---------------- SSIM formula + accumulate --------------------------------
    const float C1 = 1e-4f;   // (0.01*1)^2
    const float C2 = 9e-4f;   // (0.03*1)^2
    float vx[4];
    upk2(vxp[0], vx[0], vx[1]);
    upk2(vxp[1], vx[2], vx[3]);

    float local = 0.f;
    #pragma unroll
    for (int j = 0; j < 4; j++) {
        int gy = oy0 + r0 + j;
        int gx = ox0 + c;
        if (gy < OUT_DIM && gx < OUT_DIM) {
            float mu1, mu2, ex2, ey2;
            upk2(vm[j], mu1, mu2);
            upk2(vs[j], ex2, ey2);
            float mu1s = mu1 * mu1;
            float mu2s = mu2 * mu2;
            float mu12 = mu1 * mu2;
            float sig1 = ex2 - mu1s;
            float sig2 = ey2 - mu2s;
            float s12  = vx[j] - mu12;
            float num  = (2.f * mu12 + C1) * (2.f * s12 + C2);
            float den  = (mu1s + mu2s + C1) * (sig1 + sig2 + C2);
            local += __fdividef(num, den);
        }
    }

    // block reduction
    #pragma unroll
    for (int off = 16; off > 0; off >>= 1)
        local += __shfl_down_sync(0xffffffffu, local, off);
    if ((tid & 31) == 0)
        s_wsum[tid >> 5] = local;
    __syncthreads();

    const int bid = bx + NBX * (by + NBY * bz);
    if (tid == 0) {
        float t = 0.f;
        #pragma unroll
        for (int i = 0; i < 8; i++) t += s_wsum[i];
        g_part[bid] = t;
        __threadfence();
        unsigned old = atomicInc(&g_count, NBLK - 1);   // wraps to 0 on last
        s_last = (old == NBLK - 1);
    }
    __syncthreads();

    // ---------------- Last block: deterministic final reduce -------------------
    if (s_last) {
        double d = 0.0;
        for (int i = tid; i < NBLK; i += 256)
            d += (double)__ldcg(&g_part[i]);
        #pragma unroll
        for (int off = 16; off > 0; off >>= 1)
            d += __shfl_down_sync(0xffffffffu, d, off);
        if ((tid & 31) == 0)
            s_dred[tid >> 5] = d;
        __syncthreads();
        if (tid == 0) {
            double s = 0.0;
            #pragma unroll
            for (int i = 0; i < 8; i++) s += s_dred[i];
            out[0] = (float)(s / ((double)NIMG * OUT_DIM * OUT_DIM));
        }
    }
}

extern "C" void kernel_launch(void* const* d_in, const int* in_sizes, int n_in,
                              void* d_out, int out_size)
{
    const float* sr = (const float*)d_in[0];
    const float* hr = (const float*)d_in[1];
    dim3 grid(NBX, NBY, NIMG);
    ssim_kernel<<<grid, 256>>>(sr, hr, (float*)d_out);
}